// round 2
// baseline (speedup 1.0000x reference)
#include <cuda_runtime.h>
#include <math.h>

// Problem constants (fixed by the dataset)
#define N_NODES 10000
#define N_EDGES 160000
#define C_IN    64
#define C_OUT   128
#define K_TOT   125   // 5^3

// ---------------------------------------------------------------------------
// Static device scratch (no allocations allowed in kernel_launch)
// ---------------------------------------------------------------------------
__device__ float d_acc1[(size_t)N_NODES * K_TOT * C_IN];    // 320 MB
__device__ float d_acc2[(size_t)N_NODES * K_TOT * C_OUT];   // 640 MB
__device__ float d_msg1[N_NODES * C_OUT];
__device__ float d_msg2[N_NODES * C_OUT];
__device__ float d_h1  [N_NODES * C_OUT];
__device__ float d_sagg[N_NODES * C_IN];
__device__ float d_spre[N_NODES * C_OUT];
__device__ float d_deg [N_NODES];
__device__ float d_stats[6 * 128];   // 3 BNs x (sum, sumsq) x 128 channels

// ---------------------------------------------------------------------------
// Helpers
// ---------------------------------------------------------------------------
__device__ __forceinline__ void red4(float* a, float x, float y, float z, float w) {
    asm volatile("red.global.add.v4.f32 [%0], {%1,%2,%3,%4};"
                 :: "l"(a), "f"(x), "f"(y), "f"(z), "f"(w) : "memory");
}
__device__ __forceinline__ void red2(float* a, float x, float y) {
    asm volatile("red.global.add.v2.f32 [%0], {%1,%2};"
                 :: "l"(a), "f"(x), "f"(y) : "memory");
}
__device__ __forceinline__ float cvt_tf32(float x) {
    float r;
    asm("cvt.rna.tf32.f32 %0, %1;" : "=f"(r) : "f"(x));
    return r;
}

__global__ void zero4_kernel(float4* __restrict__ p, long n4) {
    long i = (long)blockIdx.x * blockDim.x + threadIdx.x;
    long stride = (long)gridDim.x * blockDim.x;
    for (; i < n4; i += stride) p[i] = make_float4(0.f, 0.f, 0.f, 0.f);
}

// ---------------------------------------------------------------------------
// Edge scatter: degree-1 open B-spline, 8 corners per edge.
// Each edge handled by CIN_T/4 threads (float4 per thread).
// EXTRA: also accumulate shortcut neighbor-sum (x_src) and degree.
// ---------------------------------------------------------------------------
template <int CIN_T, bool EXTRA>
__global__ void scatter_kernel(const float* __restrict__ xf, const int* __restrict__ ei,
                               const float* __restrict__ ea, float* __restrict__ acc,
                               float* __restrict__ sagg, float* __restrict__ deg) {
    const int GROUP = CIN_T / 4;
    const int EPB   = 128 / GROUP;
    int lane = threadIdx.x & (GROUP - 1);
    int g    = threadIdx.x / GROUP;
    int e    = blockIdx.x * EPB + g;
    if (e >= N_EDGES) return;
    int src = ei[e];
    int dst = ei[N_EDGES + e];
    float f[3]; int ib[3];
#pragma unroll
    for (int d = 0; d < 3; d++) {
        float v = ea[e * 3 + d] * 4.0f;   // pseudo * (K-1)
        float b = floorf(v);
        f[d]  = v - b;
        ib[d] = (int)b;
    }
    float4 xs = ((const float4*)xf)[(long)src * (CIN_T / 4) + lane];
#pragma unroll
    for (int c = 0; c < 8; c++) {
        int b0 = c & 1, b1 = (c >> 1) & 1, b2 = (c >> 2) & 1;
        float w = (b0 ? f[0] : 1.f - f[0]) *
                  (b1 ? f[1] : 1.f - f[1]) *
                  (b2 ? f[2] : 1.f - f[2]);
        int k0 = min(max(ib[0] + b0, 0), 4);
        int k1 = min(max(ib[1] + b1, 0), 4);
        int k2 = min(max(ib[2] + b2, 0), 4);
        int idx = (k0 * 5 + k1) * 5 + k2;
        red4(acc + ((long)dst * K_TOT + idx) * CIN_T + lane * 4,
             w * xs.x, w * xs.y, w * xs.z, w * xs.w);
    }
    if (EXTRA) {
        red4(sagg + (long)dst * C_IN + lane * 4, xs.x, xs.y, xs.z, xs.w);
        if (lane == 0) atomicAdd(deg + dst, 1.0f);
    }
}

// ---------------------------------------------------------------------------
// tf32 tensor-core split-K GEMM: C[M,128] += A[M,K] * B[K,128] (row-major f32)
// BM=128, BN=128, BK=32. 256 threads = 8 warps in a 4(M) x 2(N) grid.
// Warp tile 32x64 = 2 m-tiles x 8 n-tiles of mma.m16n8k8.
// Smem: A transposed [k][m] and B [k][n], both stride 136 (bank-conflict-free
// fragment loads: bank = t*8+g covers all 32 banks).
// Epilogue: red.global.add.v2.f32 into pre-zeroed C (split-K partials).
// ---------------------------------------------------------------------------
__global__ void __launch_bounds__(256)
tf32_gemm_splitk(const float* __restrict__ A, const float* __restrict__ B,
                 float* __restrict__ C, int M, int K, int kchunk) {
    __shared__ float As[32][136];
    __shared__ float Bs[32][136];
    const int m0 = blockIdx.x * 128;
    const int kstart = blockIdx.z * kchunk;
    const int kend   = kstart + kchunk;
    const int tid  = threadIdx.x;
    const int warp = tid >> 5;
    const int lane = tid & 31;
    const int g = lane >> 2;       // groupID 0..7
    const int t = lane & 3;        // threadInGroup 0..3
    const int wm0 = (warp >> 1) * 32;   // warp M offset within block
    const int wn0 = (warp & 1) * 64;    // warp N offset within block

    float c[2][8][4];
#pragma unroll
    for (int mt = 0; mt < 2; mt++)
#pragma unroll
        for (int nt = 0; nt < 8; nt++)
#pragma unroll
            for (int r = 0; r < 4; r++) c[mt][nt][r] = 0.f;

    for (int k0 = kstart; k0 < kend; k0 += 32) {
        // ---- A tile: [128 m] x [32 k] -> As[k][m], tf32-rounded
#pragma unroll
        for (int i = 0; i < 4; i++) {
            int p  = tid + i * 256;      // 0..1023
            int m  = p >> 3;             // 0..127
            int kq = p & 7;              // k-group of 4
            int gm = m0 + m;
            float4 v = make_float4(0.f, 0.f, 0.f, 0.f);
            if (gm < M) v = *(const float4*)(A + (long)gm * K + k0 + kq * 4);
            As[kq * 4 + 0][m] = cvt_tf32(v.x);
            As[kq * 4 + 1][m] = cvt_tf32(v.y);
            As[kq * 4 + 2][m] = cvt_tf32(v.z);
            As[kq * 4 + 3][m] = cvt_tf32(v.w);
        }
        // ---- B tile: [32 k] x [128 n] -> Bs[k][n], tf32-rounded
#pragma unroll
        for (int i = 0; i < 4; i++) {
            int p  = tid + i * 256;      // 0..1023
            int kk = p >> 5;             // 0..31
            int n4 = p & 31;             // n-group of 4
            float4 v = *(const float4*)(B + (long)(k0 + kk) * 128 + n4 * 4);
            float4 cv = make_float4(cvt_tf32(v.x), cvt_tf32(v.y),
                                    cvt_tf32(v.z), cvt_tf32(v.w));
            *(float4*)(&Bs[kk][n4 * 4]) = cv;
        }
        __syncthreads();

#pragma unroll
        for (int ks = 0; ks < 4; ks++) {
            int kb = ks * 8;
            unsigned a[2][4];
#pragma unroll
            for (int mt = 0; mt < 2; mt++) {
                int mr = wm0 + mt * 16 + g;
                a[mt][0] = __float_as_uint(As[kb + t    ][mr    ]);
                a[mt][1] = __float_as_uint(As[kb + t    ][mr + 8]);
                a[mt][2] = __float_as_uint(As[kb + t + 4][mr    ]);
                a[mt][3] = __float_as_uint(As[kb + t + 4][mr + 8]);
            }
#pragma unroll
            for (int nt = 0; nt < 8; nt++) {
                int nc = wn0 + nt * 8 + g;
                unsigned b0 = __float_as_uint(Bs[kb + t    ][nc]);
                unsigned b1 = __float_as_uint(Bs[kb + t + 4][nc]);
#pragma unroll
                for (int mt = 0; mt < 2; mt++) {
                    asm volatile(
                        "mma.sync.aligned.m16n8k8.row.col.f32.tf32.tf32.f32 "
                        "{%0,%1,%2,%3}, {%4,%5,%6,%7}, {%8,%9}, {%0,%1,%2,%3};"
                        : "+f"(c[mt][nt][0]), "+f"(c[mt][nt][1]),
                          "+f"(c[mt][nt][2]), "+f"(c[mt][nt][3])
                        : "r"(a[mt][0]), "r"(a[mt][1]), "r"(a[mt][2]), "r"(a[mt][3]),
                          "r"(b0), "r"(b1));
                }
            }
        }
        __syncthreads();
    }

    // epilogue: c0,c1 -> (row, 2t / 2t+1); c2,c3 -> (row+8, same cols)
#pragma unroll
    for (int mt = 0; mt < 2; mt++) {
#pragma unroll
        for (int nt = 0; nt < 8; nt++) {
            int row = m0 + wm0 + mt * 16 + g;
            int col = wn0 + nt * 8 + 2 * t;
            if (row < M)
                red2(C + (long)row * 128 + col, c[mt][nt][0], c[mt][nt][1]);
            if (row + 8 < M)
                red2(C + (long)(row + 8) * 128 + col, c[mt][nt][2], c[mt][nt][3]);
        }
    }
}

// ---------------------------------------------------------------------------
// msg = msg/max(deg,1) + x @ Wr + bias      (block per node, 128 threads)
// ---------------------------------------------------------------------------
template <int CIN_T>
__global__ void root_kernel(float* __restrict__ msg, const float* __restrict__ xin,
                            const float* __restrict__ Wr, const float* __restrict__ bias,
                            const float* __restrict__ deg) {
    __shared__ float xs[128];
    int n = blockIdx.x;
    int o = threadIdx.x;
    if (o < CIN_T) xs[o] = xin[(long)n * CIN_T + o];
    __syncthreads();
    float s = bias[o];
#pragma unroll 8
    for (int i = 0; i < CIN_T; i++) s += xs[i] * Wr[i * 128 + o];
    float dg = fmaxf(deg[n], 1.0f);
    long idx = (long)n * 128 + o;
    msg[idx] = msg[idx] / dg + s;
}

// ---------------------------------------------------------------------------
// shortcut: spre = (sagg/deg) @ Wsc + x @ Wrsc + bsc
// ---------------------------------------------------------------------------
__global__ void shortcut_kernel(const float* __restrict__ sagg, const float* __restrict__ x,
                                const float* __restrict__ Wsc, const float* __restrict__ Wrsc,
                                const float* __restrict__ bsc, const float* __restrict__ deg,
                                float* __restrict__ spre) {
    __shared__ float as_[64];
    __shared__ float xs_[64];
    int n = blockIdx.x;
    int o = threadIdx.x;
    float dg = fmaxf(deg[n], 1.0f);
    if (o < 64) {
        as_[o] = sagg[(long)n * 64 + o] / dg;
        xs_[o] = x[(long)n * 64 + o];
    }
    __syncthreads();
    float s = bsc[o];
#pragma unroll 8
    for (int i = 0; i < 64; i++)
        s += as_[i] * Wsc[i * 128 + o] + xs_[i] * Wrsc[i * 128 + o];
    spre[(long)n * 128 + o] = s;
}

// ---------------------------------------------------------------------------
// BatchNorm statistics: column sum / sumsq over N rows (128 channels)
// ---------------------------------------------------------------------------
__global__ void bn_stats_kernel(const float* __restrict__ y, float* __restrict__ st) {
    int c = threadIdx.x;
    int r0 = blockIdx.x * 100;
    float s = 0.f, s2 = 0.f;
    for (int r = 0; r < 100; r++) {
        float v = y[(long)(r0 + r) * 128 + c];
        s += v; s2 += v * v;
    }
    atomicAdd(&st[c], s);
    atomicAdd(&st[128 + c], s2);
}

__global__ void bn_elu_kernel(const float* __restrict__ y, const float* __restrict__ st,
                              const float* __restrict__ gg, const float* __restrict__ bb,
                              float* __restrict__ outp) {
    int idx = blockIdx.x * blockDim.x + threadIdx.x;   // exactly N*128
    int c = idx & 127;
    float mean = st[c] * (1.0f / N_NODES);
    float var  = st[128 + c] * (1.0f / N_NODES) - mean * mean;
    float rs   = rsqrtf(var + 1e-5f);
    float v = (y[idx] - mean) * rs * gg[c] + bb[c];
    outp[idx] = v > 0.f ? v : expm1f(v);
}

__global__ void final_kernel(const float* __restrict__ y2, const float* __restrict__ ys,
                             const float* __restrict__ st2, const float* __restrict__ sts,
                             const float* __restrict__ g2, const float* __restrict__ be2,
                             const float* __restrict__ gsc, const float* __restrict__ besc,
                             float* __restrict__ outp) {
    int idx = blockIdx.x * blockDim.x + threadIdx.x;   // exactly N*128
    int c = idx & 127;
    float m2 = st2[c] * (1.0f / N_NODES);
    float v2 = st2[128 + c] * (1.0f / N_NODES) - m2 * m2;
    float a  = (y2[idx] - m2) * rsqrtf(v2 + 1e-5f) * g2[c] + be2[c];
    float ms = sts[c] * (1.0f / N_NODES);
    float vs = sts[128 + c] * (1.0f / N_NODES) - ms * ms;
    float b  = (ys[idx] - ms) * rsqrtf(vs + 1e-5f) * gsc[c] + besc[c];
    float v = a + b;
    outp[idx] = v > 0.f ? v : expm1f(v);
}

// ---------------------------------------------------------------------------
// Launch
// ---------------------------------------------------------------------------
static inline void zero_buf(float* p, long nfloats) {
    long n4 = nfloats / 4;
    int blocks = (int)((n4 + 255) / 256);
    zero4_kernel<<<blocks, 256>>>((float4*)p, n4);
}

extern "C" void kernel_launch(void* const* d_in, const int* in_sizes, int n_in,
                              void* d_out, int out_size) {
    const float* x    = (const float*)d_in[0];
    const int*   ei   = (const int*)  d_in[1];
    const float* ea   = (const float*)d_in[2];
    const float* W1   = (const float*)d_in[3];
    const float* Wr1  = (const float*)d_in[4];
    const float* b1   = (const float*)d_in[5];
    const float* g1   = (const float*)d_in[6];
    const float* be1  = (const float*)d_in[7];
    const float* W2   = (const float*)d_in[8];
    const float* Wr2  = (const float*)d_in[9];
    const float* b2   = (const float*)d_in[10];
    const float* g2   = (const float*)d_in[11];
    const float* be2  = (const float*)d_in[12];
    const float* Wsc  = (const float*)d_in[13];
    const float* Wrsc = (const float*)d_in[14];
    const float* bsc  = (const float*)d_in[15];
    const float* gsc  = (const float*)d_in[16];
    const float* besc = (const float*)d_in[17];
    float* out = (float*)d_out;

    float *acc1, *acc2, *msg1, *msg2, *h1, *sagg, *spre, *deg, *stats;
    cudaGetSymbolAddress((void**)&acc1,  d_acc1);
    cudaGetSymbolAddress((void**)&acc2,  d_acc2);
    cudaGetSymbolAddress((void**)&msg1,  d_msg1);
    cudaGetSymbolAddress((void**)&msg2,  d_msg2);
    cudaGetSymbolAddress((void**)&h1,    d_h1);
    cudaGetSymbolAddress((void**)&sagg,  d_sagg);
    cudaGetSymbolAddress((void**)&spre,  d_spre);
    cudaGetSymbolAddress((void**)&deg,   d_deg);
    cudaGetSymbolAddress((void**)&stats, d_stats);

    // zero scratch
    zero_buf(acc1, (long)N_NODES * K_TOT * C_IN);
    zero_buf(acc2, (long)N_NODES * K_TOT * C_OUT);
    zero_buf(msg1, N_NODES * C_OUT);
    zero_buf(msg2, N_NODES * C_OUT);
    zero_buf(sagg, N_NODES * C_IN);
    zero_buf(deg,  N_NODES);
    zero_buf(stats, 6 * 128);

    // conv1 scatter (+ shortcut aggregation + degree)
    scatter_kernel<C_IN, true><<<N_EDGES / 8, 128>>>(x, ei, ea, acc1, sagg, deg);

    // conv1 GEMM (tf32 tensor cores, split-K=10) + root + bn + elu
    tf32_gemm_splitk<<<dim3((N_NODES + 127) / 128, 1, 10), 256>>>(
        acc1, W1, msg1, N_NODES, K_TOT * C_IN, 800);
    root_kernel<C_IN><<<N_NODES, 128>>>(msg1, x, Wr1, b1, deg);
    bn_stats_kernel<<<100, 128>>>(msg1, stats);
    bn_elu_kernel<<<(N_NODES * C_OUT) / 512, 512>>>(msg1, stats, g1, be1, h1);

    // conv2 scatter + GEMM + root + bn stats
    scatter_kernel<C_OUT, false><<<N_EDGES / 4, 128>>>(h1, ei, ea, acc2, nullptr, nullptr);
    tf32_gemm_splitk<<<dim3((N_NODES + 127) / 128, 1, 10), 256>>>(
        acc2, W2, msg2, N_NODES, K_TOT * C_OUT, 1600);
    root_kernel<C_OUT><<<N_NODES, 128>>>(msg2, h1, Wr2, b2, deg);
    bn_stats_kernel<<<100, 128>>>(msg2, stats + 256);

    // shortcut branch + bn stats
    shortcut_kernel<<<N_NODES, 128>>>(sagg, x, Wsc, Wrsc, bsc, deg, spre);
    bn_stats_kernel<<<100, 128>>>(spre, stats + 512);

    // final: elu(bn(conv2) + bn(shortcut))
    final_kernel<<<(N_NODES * C_OUT) / 512, 512>>>(msg2, spre, stats + 256, stats + 512,
                                                   g2, be2, gsc, besc, out);
}

// round 4
// speedup vs baseline: 1.6212x; 1.6212x over previous
#include <cuda_runtime.h>
#include <cuda_fp16.h>
#include <math.h>

// Problem constants (fixed by the dataset)
#define N_NODES 10000
#define N_EDGES 160000
#define C_IN    64
#define C_OUT   128
#define K_TOT   125   // 5^3

// ---------------------------------------------------------------------------
// Static device scratch (no allocations allowed in kernel_launch)
// ---------------------------------------------------------------------------
__device__ __half d_acc1[(size_t)N_NODES * K_TOT * C_IN];    // 160 MB fp16
__device__ __half d_acc2[(size_t)N_NODES * K_TOT * C_OUT];   // 320 MB fp16
__device__ float  d_msg1[N_NODES * C_OUT];
__device__ float  d_msg2[N_NODES * C_OUT];
__device__ __half d_h1  [N_NODES * C_OUT];
__device__ float  d_sagg[N_NODES * C_IN];
__device__ float  d_spre[N_NODES * C_OUT];
__device__ float  d_deg [N_NODES];
__device__ float  d_stats[6 * 128];
// layout: [0:128]=sum1 [128:256]=sq1 [256:384]=sum2 [384:512]=sq2
//         [512:640]=sumS [640:768]=sqS

// ---------------------------------------------------------------------------
// Helpers
// ---------------------------------------------------------------------------
__device__ __forceinline__ void red4f(float* a, float x, float y, float z, float w) {
    asm volatile("red.global.add.v4.f32 [%0], {%1,%2,%3,%4};"
                 :: "l"(a), "f"(x), "f"(y), "f"(z), "f"(w) : "memory");
}
__device__ __forceinline__ void red2f(float* a, float x, float y) {
    asm volatile("red.global.add.v2.f32 [%0], {%1,%2};"
                 :: "l"(a), "f"(x), "f"(y) : "memory");
}
__device__ __forceinline__ void red16h(__half* a, unsigned h0, unsigned h1,
                                       unsigned h2, unsigned h3) {
    asm volatile("red.global.add.noftz.v4.f16x2 [%0], {%1,%2,%3,%4};"
                 :: "l"(a), "r"(h0), "r"(h1), "r"(h2), "r"(h3) : "memory");
}
__device__ __forceinline__ unsigned h2u(__half2 h) {
    return *reinterpret_cast<unsigned*>(&h);
}

// ---------------------------------------------------------------------------
// One zero kernel for all scratch (launch #0)
// ---------------------------------------------------------------------------
#define U4_ACC1 ((long)N_NODES * K_TOT * C_IN / 8)      // half units / 8 per uint4
#define U4_ACC2 ((long)N_NODES * K_TOT * C_OUT / 8)
#define U4_MSG  ((long)N_NODES * C_OUT / 4)
#define U4_SAGG ((long)N_NODES * C_IN / 4)
#define U4_DEG  ((long)N_NODES / 4)
#define U4_ST   (6 * 128 / 4)
#define U4_TOTAL (U4_ACC1 + U4_ACC2 + 2 * U4_MSG + U4_SAGG + U4_DEG + U4_ST)

__global__ void zero_all_kernel() {
    long i = (long)blockIdx.x * blockDim.x + threadIdx.x;
    if (i >= U4_TOTAL) return;
    uint4 z = make_uint4(0u, 0u, 0u, 0u);
    if (i < U4_ACC1) { ((uint4*)d_acc1)[i] = z; return; }
    i -= U4_ACC1;
    if (i < U4_ACC2) { ((uint4*)d_acc2)[i] = z; return; }
    i -= U4_ACC2;
    if (i < U4_MSG) { ((uint4*)d_msg1)[i] = z; return; }
    i -= U4_MSG;
    if (i < U4_MSG) { ((uint4*)d_msg2)[i] = z; return; }
    i -= U4_MSG;
    if (i < U4_SAGG) { ((uint4*)d_sagg)[i] = z; return; }
    i -= U4_SAGG;
    if (i < U4_DEG) { ((uint4*)d_deg)[i] = z; return; }
    i -= U4_DEG;
    ((uint4*)d_stats)[i] = z;
}

// ---------------------------------------------------------------------------
// Spline basis per edge
// ---------------------------------------------------------------------------
__device__ __forceinline__ void spline_cell(const float* __restrict__ ea, int e,
                                            float f[3], int ib[3]) {
#pragma unroll
    for (int d = 0; d < 3; d++) {
        float v = ea[e * 3 + d] * 4.0f;
        float b = floorf(v);
        f[d] = v - b;
        ib[d] = (int)b;
    }
}
__device__ __forceinline__ int corner_idx_w(const float f[3], const int ib[3],
                                            int c, float& w) {
    int b0 = c & 1, b1 = (c >> 1) & 1, b2 = (c >> 2) & 1;
    w = (b0 ? f[0] : 1.f - f[0]) * (b1 ? f[1] : 1.f - f[1]) * (b2 ? f[2] : 1.f - f[2]);
    int k0 = min(max(ib[0] + b0, 0), 4);
    int k1 = min(max(ib[1] + b1, 0), 4);
    int k2 = min(max(ib[2] + b2, 0), 4);
    return (k0 * 5 + k1) * 5 + k2;
}

// ---------------------------------------------------------------------------
// Scatter conv1: x f32 [N,64] -> acc1 fp16; also sagg (f32) + deg.
// GROUP=8 threads/edge, each owns 8 channels (one red.v4.f16x2).
// ---------------------------------------------------------------------------
__global__ void scatter1_kernel(const float* __restrict__ xf, const int* __restrict__ ei,
                                const float* __restrict__ ea) {
    int lane = threadIdx.x & 7;
    int g    = threadIdx.x >> 3;
    int e    = blockIdx.x * 16 + g;
    int src = ei[e];
    int dst = ei[N_EDGES + e];
    float f[3]; int ib[3];
    spline_cell(ea, e, f, ib);
    const float4* xr = (const float4*)(xf + (long)src * C_IN);
    float4 v0 = xr[lane * 2];
    float4 v1 = xr[lane * 2 + 1];
#pragma unroll
    for (int c = 0; c < 8; c++) {
        float w; int idx = corner_idx_w(f, ib, c, w);
        unsigned h0 = h2u(__floats2half2_rn(w * v0.x, w * v0.y));
        unsigned h1 = h2u(__floats2half2_rn(w * v0.z, w * v0.w));
        unsigned h2 = h2u(__floats2half2_rn(w * v1.x, w * v1.y));
        unsigned h3 = h2u(__floats2half2_rn(w * v1.z, w * v1.w));
        red16h(d_acc1 + ((long)dst * K_TOT + idx) * C_IN + lane * 8, h0, h1, h2, h3);
    }
    red4f(d_sagg + (long)dst * C_IN + lane * 8, v0.x, v0.y, v0.z, v0.w);
    red4f(d_sagg + (long)dst * C_IN + lane * 8 + 4, v1.x, v1.y, v1.z, v1.w);
    if (lane == 0) atomicAdd(d_deg + dst, 1.0f);
}

// ---------------------------------------------------------------------------
// Scatter conv2: h1 fp16 [N,128] -> acc2 fp16. GROUP=16, 8 ch/thread.
// ---------------------------------------------------------------------------
__global__ void scatter2_kernel(const int* __restrict__ ei, const float* __restrict__ ea) {
    int lane = threadIdx.x & 15;
    int g    = threadIdx.x >> 4;
    int e    = blockIdx.x * 8 + g;
    int src = ei[e];
    int dst = ei[N_EDGES + e];
    float f[3]; int ib[3];
    spline_cell(ea, e, f, ib);
    uint4 hv = __ldg((const uint4*)(d_h1 + (long)src * C_OUT + lane * 8));
    float2 p0 = __half22float2(*reinterpret_cast<__half2*>(&hv.x));
    float2 p1 = __half22float2(*reinterpret_cast<__half2*>(&hv.y));
    float2 p2 = __half22float2(*reinterpret_cast<__half2*>(&hv.z));
    float2 p3 = __half22float2(*reinterpret_cast<__half2*>(&hv.w));
#pragma unroll
    for (int c = 0; c < 8; c++) {
        float w; int idx = corner_idx_w(f, ib, c, w);
        unsigned h0 = h2u(__floats2half2_rn(w * p0.x, w * p0.y));
        unsigned h1 = h2u(__floats2half2_rn(w * p1.x, w * p1.y));
        unsigned h2 = h2u(__floats2half2_rn(w * p2.x, w * p2.y));
        unsigned h3 = h2u(__floats2half2_rn(w * p3.x, w * p3.y));
        red16h(d_acc2 + ((long)dst * K_TOT + idx) * C_OUT + lane * 8, h0, h1, h2, h3);
    }
}

// ---------------------------------------------------------------------------
// fp16 tensor-core split-K GEMM: C[M,128] += A_half[M,K] * B_f32->h[K,128]
// BM=128 BN=128 BK=32, 256 threads (8 warps 4x2), warp tile 32x64,
// mma.m16n8k16, ldmatrix operand loads, red.v2.f32 split-K epilogue.
// ---------------------------------------------------------------------------
__global__ void __launch_bounds__(256)
h16_gemm_splitk(const __half* __restrict__ A, const float* __restrict__ B,
                float* __restrict__ C, int M, int K, int kchunk) {
    __shared__ __half As[128][40];    // pad 40 halves (80B): ldmatrix conflict-free
    __shared__ __half Bs[32][136];    // pad 136 halves (272B): conflict-free .trans
    const int m0 = blockIdx.x * 128;
    const int kstart = blockIdx.z * kchunk;
    const int kend   = kstart + kchunk;
    const int tid  = threadIdx.x;
    const int warp = tid >> 5;
    const int lane = tid & 31;
    const int g = lane >> 2;
    const int t = lane & 3;
    const int wm0 = (warp >> 1) * 32;
    const int wn0 = (warp & 1) * 64;

    float c[2][8][4];
#pragma unroll
    for (int mt = 0; mt < 2; mt++)
#pragma unroll
        for (int nt = 0; nt < 8; nt++)
#pragma unroll
            for (int r = 0; r < 4; r++) c[mt][nt][r] = 0.f;

    for (int k0 = kstart; k0 < kend; k0 += 32) {
        // A tile: 128 rows x 32 halves; uint4 gmem load, uint2 smem stores
#pragma unroll
        for (int i = 0; i < 2; i++) {
            int p   = tid + i * 256;        // 0..511
            int row = p >> 2;               // 0..127
            int seg = p & 3;                // 8-half segment
            int gm  = m0 + row;
            uint4 v = make_uint4(0u, 0u, 0u, 0u);
            if (gm < M) v = *(const uint4*)(A + (long)gm * K + k0 + seg * 8);
            *(uint2*)(&As[row][seg * 8])     = make_uint2(v.x, v.y);
            *(uint2*)(&As[row][seg * 8 + 4]) = make_uint2(v.z, v.w);
        }
        // B tile: 32 x 128 f32 -> half
#pragma unroll
        for (int i = 0; i < 4; i++) {
            int p  = tid + i * 256;         // 0..1023
            int kk = p >> 5;                // 0..31
            int n4 = p & 31;
            float4 v = *(const float4*)(B + (long)(k0 + kk) * 128 + n4 * 4);
            unsigned u0 = h2u(__floats2half2_rn(v.x, v.y));
            unsigned u1 = h2u(__floats2half2_rn(v.z, v.w));
            *(uint2*)(&Bs[kk][n4 * 4]) = make_uint2(u0, u1);
        }
        __syncthreads();

#pragma unroll
        for (int ks = 0; ks < 2; ks++) {
            int kb = ks * 16;
            // A fragments (2 m-tiles)
            unsigned a[2][4];
#pragma unroll
            for (int mt = 0; mt < 2; mt++) {
                unsigned addr = (unsigned)__cvta_generic_to_shared(
                    &As[wm0 + mt * 16 + (lane & 15)][kb + (lane >> 4) * 8]);
                asm volatile("ldmatrix.sync.aligned.m8n8.x4.shared.b16 {%0,%1,%2,%3}, [%4];"
                             : "=r"(a[mt][0]), "=r"(a[mt][1]), "=r"(a[mt][2]), "=r"(a[mt][3])
                             : "r"(addr));
            }
            // B fragments (8 n-tiles, loaded 2 at a time via x4.trans)
            unsigned b[8][2];
#pragma unroll
            for (int nt2 = 0; nt2 < 4; nt2++) {
                unsigned addr = (unsigned)__cvta_generic_to_shared(
                    &Bs[kb + (lane & 15)][wn0 + nt2 * 16 + (lane >> 4) * 8]);
                asm volatile("ldmatrix.sync.aligned.m8n8.x4.trans.shared.b16 {%0,%1,%2,%3}, [%4];"
                             : "=r"(b[nt2 * 2][0]), "=r"(b[nt2 * 2][1]),
                               "=r"(b[nt2 * 2 + 1][0]), "=r"(b[nt2 * 2 + 1][1])
                             : "r"(addr));
            }
#pragma unroll
            for (int nt = 0; nt < 8; nt++)
#pragma unroll
                for (int mt = 0; mt < 2; mt++) {
                    asm volatile(
                        "mma.sync.aligned.m16n8k16.row.col.f32.f16.f16.f32 "
                        "{%0,%1,%2,%3}, {%4,%5,%6,%7}, {%8,%9}, {%0,%1,%2,%3};"
                        : "+f"(c[mt][nt][0]), "+f"(c[mt][nt][1]),
                          "+f"(c[mt][nt][2]), "+f"(c[mt][nt][3])
                        : "r"(a[mt][0]), "r"(a[mt][1]), "r"(a[mt][2]), "r"(a[mt][3]),
                          "r"(b[nt][0]), "r"(b[nt][1]));
                }
        }
        __syncthreads();
    }

#pragma unroll
    for (int mt = 0; mt < 2; mt++)
#pragma unroll
        for (int nt = 0; nt < 8; nt++) {
            int row = m0 + wm0 + mt * 16 + g;
            int col = wn0 + nt * 8 + 2 * t;
            if (row < M)
                red2f(C + (long)row * 128 + col, c[mt][nt][0], c[mt][nt][1]);
            if (row + 8 < M)
                red2f(C + (long)(row + 8) * 128 + col, c[mt][nt][2], c[mt][nt][3]);
        }
}

// ---------------------------------------------------------------------------
// root + BN-stats: msg = msg/max(deg,1) + x @ Wr + bias; atomic stats.
// ---------------------------------------------------------------------------
template <int CIN_T, typename TIN>
__global__ void root_stats_kernel(float* __restrict__ msg, const TIN* __restrict__ xin,
                                  const float* __restrict__ Wr, const float* __restrict__ bias,
                                  const float* __restrict__ deg, float* __restrict__ st) {
    __shared__ float xs[128];
    int n = blockIdx.x;
    int o = threadIdx.x;
    if (o < CIN_T) xs[o] = (float)xin[(long)n * CIN_T + o];
    __syncthreads();
    float s = bias[o];
#pragma unroll 8
    for (int i = 0; i < CIN_T; i++) s += xs[i] * Wr[i * 128 + o];
    float dg = fmaxf(deg[n], 1.0f);
    long idx = (long)n * 128 + o;
    float v = msg[idx] / dg + s;
    msg[idx] = v;
    atomicAdd(&st[o], v);
    atomicAdd(&st[128 + o], v * v);
}

// ---------------------------------------------------------------------------
// bn + elu -> h1 (fp16)
// ---------------------------------------------------------------------------
__global__ void bn_elu_kernel(const float* __restrict__ y, const float* __restrict__ st,
                              const float* __restrict__ gg, const float* __restrict__ bb,
                              __half* __restrict__ outp) {
    int idx = blockIdx.x * blockDim.x + threadIdx.x;
    int c = idx & 127;
    float mean = st[c] * (1.0f / N_NODES);
    float var  = st[128 + c] * (1.0f / N_NODES) - mean * mean;
    float rs   = rsqrtf(var + 1e-5f);
    float v = (y[idx] - mean) * rs * gg[c] + bb[c];
    outp[idx] = __float2half(v > 0.f ? v : expm1f(v));
}

// ---------------------------------------------------------------------------
// shortcut + stats: spre = (sagg/deg) @ Wsc + x @ Wrsc + bsc
// ---------------------------------------------------------------------------
__global__ void shortcut_stats_kernel(const float* __restrict__ x,
                                      const float* __restrict__ Wsc,
                                      const float* __restrict__ Wrsc,
                                      const float* __restrict__ bsc,
                                      float* __restrict__ st) {
    __shared__ float as_[64];
    __shared__ float xs_[64];
    int n = blockIdx.x;
    int o = threadIdx.x;
    float dg = fmaxf(d_deg[n], 1.0f);
    if (o < 64) {
        as_[o] = d_sagg[(long)n * 64 + o] / dg;
        xs_[o] = x[(long)n * 64 + o];
    }
    __syncthreads();
    float s = bsc[o];
#pragma unroll 8
    for (int i = 0; i < 64; i++)
        s += as_[i] * Wsc[i * 128 + o] + xs_[i] * Wrsc[i * 128 + o];
    d_spre[(long)n * 128 + o] = s;
    atomicAdd(&st[o], s);
    atomicAdd(&st[128 + o], s * s);
}

// ---------------------------------------------------------------------------
// final: elu(bn(conv2) + bn(shortcut))
// ---------------------------------------------------------------------------
__global__ void final_kernel(const float* __restrict__ st2, const float* __restrict__ sts,
                             const float* __restrict__ g2, const float* __restrict__ be2,
                             const float* __restrict__ gsc, const float* __restrict__ besc,
                             float* __restrict__ outp) {
    int idx = blockIdx.x * blockDim.x + threadIdx.x;
    int c = idx & 127;
    float m2 = st2[c] * (1.0f / N_NODES);
    float v2 = st2[128 + c] * (1.0f / N_NODES) - m2 * m2;
    float a  = (d_msg2[idx] - m2) * rsqrtf(v2 + 1e-5f) * g2[c] + be2[c];
    float ms = sts[c] * (1.0f / N_NODES);
    float vs = sts[128 + c] * (1.0f / N_NODES) - ms * ms;
    float b  = (d_spre[idx] - ms) * rsqrtf(vs + 1e-5f) * gsc[c] + besc[c];
    float v = a + b;
    outp[idx] = v > 0.f ? v : expm1f(v);
}

// ---------------------------------------------------------------------------
// Launch (10 launches; #5 = scatter2 for ncu -s 5 -c 1 capture)
// ---------------------------------------------------------------------------
extern "C" void kernel_launch(void* const* d_in, const int* in_sizes, int n_in,
                              void* d_out, int out_size) {
    const float* x    = (const float*)d_in[0];
    const int*   ei   = (const int*)  d_in[1];
    const float* ea   = (const float*)d_in[2];
    const float* W1   = (const float*)d_in[3];
    const float* Wr1  = (const float*)d_in[4];
    const float* b1   = (const float*)d_in[5];
    const float* g1   = (const float*)d_in[6];
    const float* be1  = (const float*)d_in[7];
    const float* W2   = (const float*)d_in[8];
    const float* Wr2  = (const float*)d_in[9];
    const float* b2   = (const float*)d_in[10];
    const float* g2   = (const float*)d_in[11];
    const float* be2  = (const float*)d_in[12];
    const float* Wsc  = (const float*)d_in[13];
    const float* Wrsc = (const float*)d_in[14];
    const float* bsc  = (const float*)d_in[15];
    const float* gsc  = (const float*)d_in[16];
    const float* besc = (const float*)d_in[17];
    float* out = (float*)d_out;

    __half *acc1, *acc2, *h1;
    float *msg1, *msg2, *deg, *stats;
    cudaGetSymbolAddress((void**)&acc1,  d_acc1);
    cudaGetSymbolAddress((void**)&acc2,  d_acc2);
    cudaGetSymbolAddress((void**)&h1,    d_h1);
    cudaGetSymbolAddress((void**)&msg1,  d_msg1);
    cudaGetSymbolAddress((void**)&msg2,  d_msg2);
    cudaGetSymbolAddress((void**)&deg,   d_deg);
    cudaGetSymbolAddress((void**)&stats, d_stats);

    // 0: zero all scratch
    zero_all_kernel<<<(unsigned)((U4_TOTAL + 255) / 256), 256>>>();
    // 1: conv1 scatter (+sagg +deg)
    scatter1_kernel<<<N_EDGES / 16, 128>>>(x, ei, ea);
    // 2: conv1 GEMM (fp16 mma, split-K 10)
    h16_gemm_splitk<<<dim3((N_NODES + 127) / 128, 1, 10), 256>>>(
        acc1, W1, msg1, N_NODES, K_TOT * C_IN, 800);
    // 3: root1 + bn1 stats
    root_stats_kernel<C_IN, float><<<N_NODES, 128>>>(msg1, x, Wr1, b1, deg, stats);
    // 4: bn1 + elu -> h1 (fp16)
    bn_elu_kernel<<<(N_NODES * C_OUT) / 512, 512>>>(msg1, stats, g1, be1, h1);
    // 5: conv2 scatter   <-- ncu capture target
    scatter2_kernel<<<N_EDGES / 8, 128>>>(ei, ea);
    // 6: conv2 GEMM
    h16_gemm_splitk<<<dim3((N_NODES + 127) / 128, 1, 10), 256>>>(
        acc2, W2, msg2, N_NODES, K_TOT * C_OUT, 1600);
    // 7: root2 + bn2 stats
    root_stats_kernel<C_OUT, __half><<<N_NODES, 128>>>(msg2, h1, Wr2, b2, deg, stats + 256);
    // 8: shortcut + bn stats
    shortcut_stats_kernel<<<N_NODES, 128>>>(x, Wsc, Wrsc, bsc, stats + 512);
    // 9: final
    final_kernel<<<(N_NODES * C_OUT) / 512, 512>>>(stats + 256, stats + 512,
                                                   g2, be2, gsc, besc, out);
}

// round 5
// speedup vs baseline: 2.2948x; 1.4155x over previous
#include <cuda_runtime.h>
#include <cuda_fp16.h>
#include <math.h>

// Problem constants (fixed by the dataset)
#define N_NODES 10000
#define N_EDGES 160000
#define C_IN    64
#define C_OUT   128
#define K_TOT   125   // 5^3

// ---------------------------------------------------------------------------
// Static device scratch
// ---------------------------------------------------------------------------
__device__ __half d_acc1[(size_t)N_NODES * K_TOT * C_IN];    // 160 MB fp16
__device__ __half d_acc2[(size_t)N_NODES * K_TOT * C_OUT];   // 320 MB fp16
__device__ float  d_msg1[N_NODES * C_OUT];
__device__ float  d_msg2[N_NODES * C_OUT];
__device__ __half d_h1  [N_NODES * C_OUT];
__device__ __half d_xcat[N_NODES * 128];    // cols 0..63 = x (half); 64..127 = sum(x_src)/deg
__device__ float  d_wcat[128 * 128];        // rows 0..63 = Wrsc; rows 64..127 = Wsc
__device__ float  d_spre[N_NODES * C_OUT];
__device__ float  d_deg [N_NODES];
__device__ float  d_stats[6 * 128];
// layout: [0:128]=sum1 [128:256]=sq1 [256:384]=sum2 [384:512]=sq2
//         [512:640]=sumS [640:768]=sqS

// ---------------------------------------------------------------------------
// Helpers
// ---------------------------------------------------------------------------
__device__ __forceinline__ void red2f(float* a, float x, float y) {
    asm volatile("red.global.add.v2.f32 [%0], {%1,%2};"
                 :: "l"(a), "f"(x), "f"(y) : "memory");
}
__device__ __forceinline__ void red16h(__half* a, unsigned h0, unsigned h1,
                                       unsigned h2, unsigned h3) {
    asm volatile("red.global.add.noftz.v4.f16x2 [%0], {%1,%2,%3,%4};"
                 :: "l"(a), "r"(h0), "r"(h1), "r"(h2), "r"(h3) : "memory");
}
__device__ __forceinline__ unsigned h2u(__half2 h) {
    return *reinterpret_cast<unsigned*>(&h);
}

// ---------------------------------------------------------------------------
// Zero all scratch (launch #0)
// ---------------------------------------------------------------------------
#define U4_ACC1 ((long)N_NODES * K_TOT * C_IN / 8)
#define U4_ACC2 ((long)N_NODES * K_TOT * C_OUT / 8)
#define U4_MSG  ((long)N_NODES * C_OUT / 4)
#define U4_XCAT ((long)N_NODES * 128 / 8)
#define U4_SPRE ((long)N_NODES * C_OUT / 4)
#define U4_DEG  ((long)N_NODES / 4)
#define U4_ST   (6 * 128 / 4)
#define U4_TOTAL (U4_ACC1 + U4_ACC2 + 2 * U4_MSG + U4_XCAT + U4_SPRE + U4_DEG + U4_ST)

__global__ void zero_all_kernel() {
    long i = (long)blockIdx.x * blockDim.x + threadIdx.x;
    if (i >= U4_TOTAL) return;
    uint4 z = make_uint4(0u, 0u, 0u, 0u);
    if (i < U4_ACC1) { ((uint4*)d_acc1)[i] = z; return; }
    i -= U4_ACC1;
    if (i < U4_ACC2) { ((uint4*)d_acc2)[i] = z; return; }
    i -= U4_ACC2;
    if (i < U4_MSG) { ((uint4*)d_msg1)[i] = z; return; }
    i -= U4_MSG;
    if (i < U4_MSG) { ((uint4*)d_msg2)[i] = z; return; }
    i -= U4_MSG;
    if (i < U4_XCAT) { ((uint4*)d_xcat)[i] = z; return; }
    i -= U4_XCAT;
    if (i < U4_SPRE) { ((uint4*)d_spre)[i] = z; return; }
    i -= U4_SPRE;
    if (i < U4_DEG) { ((uint4*)d_deg)[i] = z; return; }
    i -= U4_DEG;
    ((uint4*)d_stats)[i] = z;
}

// ---------------------------------------------------------------------------
// Degree count
// ---------------------------------------------------------------------------
__global__ void deg_kernel(const int* __restrict__ ei) {
    int e = blockIdx.x * blockDim.x + threadIdx.x;
    if (e < N_EDGES) atomicAdd(d_deg + ei[N_EDGES + e], 1.0f);
}

// ---------------------------------------------------------------------------
// Prep: x -> xcat cols 0..63 (half); build wcat = [Wrsc ; Wsc]
// ---------------------------------------------------------------------------
__global__ void prep_kernel(const float* __restrict__ x,
                            const float* __restrict__ Wsc,
                            const float* __restrict__ Wrsc) {
    int i = blockIdx.x * blockDim.x + threadIdx.x;
    // x conversion: N_NODES*64 elems
    if (i < N_NODES * 64) {
        int n = i >> 6, c = i & 63;
        d_xcat[n * 128 + c] = __float2half(x[i]);
    }
    // wcat: 128*128 elems handled by first 16384 threads
    if (i < 128 * 128) {
        int r = i >> 7;
        d_wcat[i] = (r < 64) ? Wrsc[i] : Wsc[i - 64 * 128];
    }
}

// ---------------------------------------------------------------------------
// Spline basis helpers
// ---------------------------------------------------------------------------
__device__ __forceinline__ void spline_cell(const float* __restrict__ ea, int e,
                                            float f[3], int ib[3]) {
#pragma unroll
    for (int d = 0; d < 3; d++) {
        float v = ea[e * 3 + d] * 4.0f;
        float b = floorf(v);
        f[d] = v - b;
        ib[d] = (int)b;
    }
}
__device__ __forceinline__ int corner_idx_w(const float f[3], const int ib[3],
                                            int c, float& w) {
    int b0 = c & 1, b1 = (c >> 1) & 1, b2 = (c >> 2) & 1;
    w = (b0 ? f[0] : 1.f - f[0]) * (b1 ? f[1] : 1.f - f[1]) * (b2 ? f[2] : 1.f - f[2]);
    int k0 = min(max(ib[0] + b0, 0), 4);
    int k1 = min(max(ib[1] + b1, 0), 4);
    int k2 = min(max(ib[2] + b2, 0), 4);
    return (k0 * 5 + k1) * 5 + k2;
}

// ---------------------------------------------------------------------------
// Scatter conv1: acc1 += (w/deg)*x_src (fp16); xcat[64:128] += x_src/deg (fp16)
// GROUP=8 threads/edge, 8 channels each.
// ---------------------------------------------------------------------------
__global__ void scatter1_kernel(const float* __restrict__ xf, const int* __restrict__ ei,
                                const float* __restrict__ ea) {
    int lane = threadIdx.x & 7;
    int g    = threadIdx.x >> 3;
    int e    = blockIdx.x * 16 + g;
    int src = ei[e];
    int dst = ei[N_EDGES + e];
    float invd = 1.0f / fmaxf(d_deg[dst], 1.0f);
    float f[3]; int ib[3];
    spline_cell(ea, e, f, ib);
    const float4* xr = (const float4*)(xf + (long)src * C_IN);
    float4 v0 = xr[lane * 2];
    float4 v1 = xr[lane * 2 + 1];
    v0.x *= invd; v0.y *= invd; v0.z *= invd; v0.w *= invd;
    v1.x *= invd; v1.y *= invd; v1.z *= invd; v1.w *= invd;
#pragma unroll
    for (int c = 0; c < 8; c++) {
        float w; int idx = corner_idx_w(f, ib, c, w);
        unsigned h0 = h2u(__floats2half2_rn(w * v0.x, w * v0.y));
        unsigned h1 = h2u(__floats2half2_rn(w * v0.z, w * v0.w));
        unsigned h2 = h2u(__floats2half2_rn(w * v1.x, w * v1.y));
        unsigned h3 = h2u(__floats2half2_rn(w * v1.z, w * v1.w));
        red16h(d_acc1 + ((long)dst * K_TOT + idx) * C_IN + lane * 8, h0, h1, h2, h3);
    }
    // shortcut neighbor mean into xcat cols 64..127
    unsigned s0 = h2u(__floats2half2_rn(v0.x, v0.y));
    unsigned s1 = h2u(__floats2half2_rn(v0.z, v0.w));
    unsigned s2 = h2u(__floats2half2_rn(v1.x, v1.y));
    unsigned s3 = h2u(__floats2half2_rn(v1.z, v1.w));
    red16h(d_xcat + (long)dst * 128 + 64 + lane * 8, s0, s1, s2, s3);
}

// ---------------------------------------------------------------------------
// Scatter conv2: acc2 += (w/deg)*h1_src (fp16). GROUP=16, 8 ch/thread.
// ---------------------------------------------------------------------------
__global__ void scatter2_kernel(const int* __restrict__ ei, const float* __restrict__ ea) {
    int lane = threadIdx.x & 15;
    int g    = threadIdx.x >> 4;
    int e    = blockIdx.x * 8 + g;
    int src = ei[e];
    int dst = ei[N_EDGES + e];
    float invd = 1.0f / fmaxf(d_deg[dst], 1.0f);
    float f[3]; int ib[3];
    spline_cell(ea, e, f, ib);
    uint4 hv = __ldg((const uint4*)(d_h1 + (long)src * C_OUT + lane * 8));
    float2 p0 = __half22float2(*reinterpret_cast<__half2*>(&hv.x));
    float2 p1 = __half22float2(*reinterpret_cast<__half2*>(&hv.y));
    float2 p2 = __half22float2(*reinterpret_cast<__half2*>(&hv.z));
    float2 p3 = __half22float2(*reinterpret_cast<__half2*>(&hv.w));
#pragma unroll
    for (int c = 0; c < 8; c++) {
        float w; int idx = corner_idx_w(f, ib, c, w);
        float ws = w * invd;
        unsigned h0 = h2u(__floats2half2_rn(ws * p0.x, ws * p0.y));
        unsigned h1 = h2u(__floats2half2_rn(ws * p1.x, ws * p1.y));
        unsigned h2 = h2u(__floats2half2_rn(ws * p2.x, ws * p2.y));
        unsigned h3 = h2u(__floats2half2_rn(ws * p3.x, ws * p3.y));
        red16h(d_acc2 + ((long)dst * K_TOT + idx) * C_OUT + lane * 8, h0, h1, h2, h3);
    }
}

// ---------------------------------------------------------------------------
// fp16 tensor-core split-K GEMM: C[M,128] += A_half[M,K(lda)] * B_f32->h[K,128]
// BM=128 BN=128 BK=32, 256 threads (8 warps 4x2), mma.m16n8k16, ldmatrix,
// red.v2.f32 additive epilogue.
// ---------------------------------------------------------------------------
__global__ void __launch_bounds__(256)
h16_gemm_splitk(const __half* __restrict__ A, const float* __restrict__ B,
                float* __restrict__ C, int M, int lda, int kchunk) {
    __shared__ __half As[128][40];
    __shared__ __half Bs[32][136];
    const int m0 = blockIdx.x * 128;
    const int kstart = blockIdx.z * kchunk;
    const int kend   = kstart + kchunk;
    const int tid  = threadIdx.x;
    const int warp = tid >> 5;
    const int lane = tid & 31;
    const int g = lane >> 2;
    const int t = lane & 3;
    const int wm0 = (warp >> 1) * 32;
    const int wn0 = (warp & 1) * 64;

    float c[2][8][4];
#pragma unroll
    for (int mt = 0; mt < 2; mt++)
#pragma unroll
        for (int nt = 0; nt < 8; nt++)
#pragma unroll
            for (int r = 0; r < 4; r++) c[mt][nt][r] = 0.f;

    for (int k0 = kstart; k0 < kend; k0 += 32) {
#pragma unroll
        for (int i = 0; i < 2; i++) {
            int p   = tid + i * 256;
            int row = p >> 2;
            int seg = p & 3;
            int gm  = m0 + row;
            uint4 v = make_uint4(0u, 0u, 0u, 0u);
            if (gm < M) v = *(const uint4*)(A + (long)gm * lda + k0 + seg * 8);
            *(uint2*)(&As[row][seg * 8])     = make_uint2(v.x, v.y);
            *(uint2*)(&As[row][seg * 8 + 4]) = make_uint2(v.z, v.w);
        }
#pragma unroll
        for (int i = 0; i < 4; i++) {
            int p  = tid + i * 256;
            int kk = p >> 5;
            int n4 = p & 31;
            float4 v = *(const float4*)(B + (long)(k0 + kk) * 128 + n4 * 4);
            unsigned u0 = h2u(__floats2half2_rn(v.x, v.y));
            unsigned u1 = h2u(__floats2half2_rn(v.z, v.w));
            *(uint2*)(&Bs[kk][n4 * 4]) = make_uint2(u0, u1);
        }
        __syncthreads();

#pragma unroll
        for (int ks = 0; ks < 2; ks++) {
            int kb = ks * 16;
            unsigned a[2][4];
#pragma unroll
            for (int mt = 0; mt < 2; mt++) {
                unsigned addr = (unsigned)__cvta_generic_to_shared(
                    &As[wm0 + mt * 16 + (lane & 15)][kb + (lane >> 4) * 8]);
                asm volatile("ldmatrix.sync.aligned.m8n8.x4.shared.b16 {%0,%1,%2,%3}, [%4];"
                             : "=r"(a[mt][0]), "=r"(a[mt][1]), "=r"(a[mt][2]), "=r"(a[mt][3])
                             : "r"(addr));
            }
            unsigned b[8][2];
#pragma unroll
            for (int nt2 = 0; nt2 < 4; nt2++) {
                unsigned addr = (unsigned)__cvta_generic_to_shared(
                    &Bs[kb + (lane & 15)][wn0 + nt2 * 16 + (lane >> 4) * 8]);
                asm volatile("ldmatrix.sync.aligned.m8n8.x4.trans.shared.b16 {%0,%1,%2,%3}, [%4];"
                             : "=r"(b[nt2 * 2][0]), "=r"(b[nt2 * 2][1]),
                               "=r"(b[nt2 * 2 + 1][0]), "=r"(b[nt2 * 2 + 1][1])
                             : "r"(addr));
            }
#pragma unroll
            for (int nt = 0; nt < 8; nt++)
#pragma unroll
                for (int mt = 0; mt < 2; mt++) {
                    asm volatile(
                        "mma.sync.aligned.m16n8k16.row.col.f32.f16.f16.f32 "
                        "{%0,%1,%2,%3}, {%4,%5,%6,%7}, {%8,%9}, {%0,%1,%2,%3};"
                        : "+f"(c[mt][nt][0]), "+f"(c[mt][nt][1]),
                          "+f"(c[mt][nt][2]), "+f"(c[mt][nt][3])
                        : "r"(a[mt][0]), "r"(a[mt][1]), "r"(a[mt][2]), "r"(a[mt][3]),
                          "r"(b[nt][0]), "r"(b[nt][1]));
                }
        }
        __syncthreads();
    }

#pragma unroll
    for (int mt = 0; mt < 2; mt++)
#pragma unroll
        for (int nt = 0; nt < 8; nt++) {
            int row = m0 + wm0 + mt * 16 + g;
            int col = wn0 + nt * 8 + 2 * t;
            if (row < M)
                red2f(C + (long)row * 128 + col, c[mt][nt][0], c[mt][nt][1]);
            if (row + 8 < M)
                red2f(C + (long)(row + 8) * 128 + col, c[mt][nt][2], c[mt][nt][3]);
        }
}

// ---------------------------------------------------------------------------
// BN column stats: sum/sumsq per channel (one or two buffers)
// ---------------------------------------------------------------------------
__global__ void bn_stats_kernel(const float* __restrict__ y, float* __restrict__ st) {
    int c = threadIdx.x;
    int r0 = blockIdx.x * 100;
    float s = 0.f, s2 = 0.f;
    for (int r = 0; r < 100; r++) {
        float v = y[(long)(r0 + r) * 128 + c];
        s += v; s2 += v * v;
    }
    atomicAdd(&st[c], s);
    atomicAdd(&st[128 + c], s2);
}

__global__ void bn_stats2_kernel(const float* __restrict__ ya, const float* __restrict__ yb,
                                 float* __restrict__ sta, float* __restrict__ stb) {
    int c = threadIdx.x;
    int r0 = blockIdx.x * 100;
    float s = 0.f, s2 = 0.f, u = 0.f, u2 = 0.f;
    for (int r = 0; r < 100; r++) {
        float v = ya[(long)(r0 + r) * 128 + c];
        s += v; s2 += v * v;
        float w = yb[(long)(r0 + r) * 128 + c];
        u += w; u2 += w * w;
    }
    atomicAdd(&sta[c], s);
    atomicAdd(&sta[128 + c], s2);
    atomicAdd(&stb[c], u);
    atomicAdd(&stb[128 + c], u2);
}

// ---------------------------------------------------------------------------
// bn + elu -> h1 (fp16)
// ---------------------------------------------------------------------------
__global__ void bn_elu_kernel(const float* __restrict__ y, const float* __restrict__ st,
                              const float* __restrict__ gg, const float* __restrict__ bb,
                              __half* __restrict__ outp) {
    int idx = blockIdx.x * blockDim.x + threadIdx.x;
    int c = idx & 127;
    float mean = st[c] * (1.0f / N_NODES);
    float var  = st[128 + c] * (1.0f / N_NODES) - mean * mean;
    float rs   = rsqrtf(var + 1e-5f);
    float v = (y[idx] - mean) * rs * gg[c] + bb[c];
    outp[idx] = __float2half(v > 0.f ? v : expm1f(v));
}

// ---------------------------------------------------------------------------
// final: elu(bn(conv2) + bn(shortcut))
// ---------------------------------------------------------------------------
__global__ void final_kernel(const float* __restrict__ st2, const float* __restrict__ sts,
                             const float* __restrict__ g2, const float* __restrict__ be2,
                             const float* __restrict__ gsc, const float* __restrict__ besc,
                             float* __restrict__ outp) {
    int idx = blockIdx.x * blockDim.x + threadIdx.x;
    int c = idx & 127;
    float m2 = st2[c] * (1.0f / N_NODES);
    float v2 = st2[128 + c] * (1.0f / N_NODES) - m2 * m2;
    float a  = (d_msg2[idx] - m2) * rsqrtf(v2 + 1e-5f) * g2[c] + be2[c];
    float ms = sts[c] * (1.0f / N_NODES);
    float vs = sts[128 + c] * (1.0f / N_NODES) - ms * ms;
    float b  = (d_spre[idx] - ms) * rsqrtf(vs + 1e-5f) * gsc[c] + besc[c];
    float v = a + b;
    outp[idx] = v > 0.f ? v : expm1f(v);
}

// ---------------------------------------------------------------------------
// Launch
// ---------------------------------------------------------------------------
extern "C" void kernel_launch(void* const* d_in, const int* in_sizes, int n_in,
                              void* d_out, int out_size) {
    const float* x    = (const float*)d_in[0];
    const int*   ei   = (const int*)  d_in[1];
    const float* ea   = (const float*)d_in[2];
    const float* W1   = (const float*)d_in[3];
    const float* Wr1  = (const float*)d_in[4];
    const float* g1   = (const float*)d_in[6];
    const float* be1  = (const float*)d_in[7];
    const float* W2   = (const float*)d_in[8];
    const float* Wr2  = (const float*)d_in[9];
    const float* g2   = (const float*)d_in[11];
    const float* be2  = (const float*)d_in[12];
    const float* Wsc  = (const float*)d_in[13];
    const float* Wrsc = (const float*)d_in[14];
    const float* gsc  = (const float*)d_in[16];
    const float* besc = (const float*)d_in[17];
    float* out = (float*)d_out;

    __half *acc1, *acc2, *h1, *xcat;
    float *msg1, *msg2, *spre, *stats, *wcat;
    cudaGetSymbolAddress((void**)&acc1,  d_acc1);
    cudaGetSymbolAddress((void**)&acc2,  d_acc2);
    cudaGetSymbolAddress((void**)&h1,    d_h1);
    cudaGetSymbolAddress((void**)&xcat,  d_xcat);
    cudaGetSymbolAddress((void**)&msg1,  d_msg1);
    cudaGetSymbolAddress((void**)&msg2,  d_msg2);
    cudaGetSymbolAddress((void**)&spre,  d_spre);
    cudaGetSymbolAddress((void**)&stats, d_stats);
    cudaGetSymbolAddress((void**)&wcat,  d_wcat);

    const int GB = (N_NODES + 127) / 128;   // 79 M-blocks

    // 0: zero all scratch
    zero_all_kernel<<<(unsigned)((U4_TOTAL + 255) / 256), 256>>>();
    // 1: degree count
    deg_kernel<<<(N_EDGES + 255) / 256, 256>>>(ei);
    // 2: prep (x->half into xcat, build wcat)
    prep_kernel<<<(N_NODES * 64 + 255) / 256, 256>>>(x, Wsc, Wrsc);
    // 3: conv1 scatter (mean-folded; also xcat[64:128] neighbor mean)
    scatter1_kernel<<<N_EDGES / 16, 128>>>(x, ei, ea);
    // 4: conv1 GEMM (split-K 10) -> msg1
    h16_gemm_splitk<<<dim3(GB, 1, 10), 256>>>(acc1, W1, msg1,
                                              N_NODES, K_TOT * C_IN, 800);
    // 5: root1 GEMM: xcat[:, :64] @ Wr1 -> msg1 (K=64, lda=128)
    h16_gemm_splitk<<<dim3(GB, 1, 1), 256>>>(xcat, Wr1, msg1, N_NODES, 128, 64);
    // 6: bn1 stats
    bn_stats_kernel<<<100, 128>>>(msg1, stats);
    // 7: bn1 + elu -> h1 (fp16)
    bn_elu_kernel<<<(N_NODES * C_OUT) / 512, 512>>>(msg1, stats, g1, be1, h1);
    // 8: conv2 scatter
    scatter2_kernel<<<N_EDGES / 8, 128>>>(ei, ea);
    // 9: conv2 GEMM (split-K 10) -> msg2
    h16_gemm_splitk<<<dim3(GB, 1, 10), 256>>>(acc2, W2, msg2,
                                              N_NODES, K_TOT * C_OUT, 1600);
    // 10: root2 GEMM: h1 @ Wr2 -> msg2 (K=128)
    h16_gemm_splitk<<<dim3(GB, 1, 1), 256>>>(h1, Wr2, msg2, N_NODES, 128, 128);
    // 11: shortcut GEMM: xcat @ wcat -> spre (K=128)
    h16_gemm_splitk<<<dim3(GB, 1, 1), 256>>>(xcat, wcat, spre, N_NODES, 128, 128);
    // 12: bn2 + bnS stats
    bn_stats2_kernel<<<100, 128>>>(msg2, spre, stats + 256, stats + 512);
    // 13: final
    final_kernel<<<(N_NODES * C_OUT) / 512, 512>>>(stats + 256, stats + 512,
                                                   g2, be2, gsc, besc, out);
}